// round 2
// baseline (speedup 1.0000x reference)
#include <cuda_runtime.h>
#include <math.h>

#define NMAX 100000
#define EMAX 1000000
#define F    64
#define FO   16

// ---------------- scratch (no allocations allowed) ----------------
__device__ int   g_hist[NMAX];          // per-row edge count (no self loop)
__device__ int   g_cnt [NMAX];          // fill cursors
__device__ int   g_rowptr[NMAX + 1];
__device__ int   g_col [EMAX];
__device__ float g_w   [EMAX];
__device__ float g_dinv[NMAX];
__device__ float g_bufA[(size_t)NMAX * F];
__device__ float g_bufB[(size_t)NMAX * F];
__device__ int   g_part[1024];          // scan partials (<= 196 used)

// ---------------- CSR build ----------------
__global__ void k_init(int n) {
    int i = blockIdx.x * blockDim.x + threadIdx.x;
    if (i < n) { g_hist[i] = 0; g_cnt[i] = 0; }
}

__global__ void k_hist(const int* __restrict__ ei, int E) {
    int e = blockIdx.x * blockDim.x + threadIdx.x;
    if (e < E) atomicAdd(&g_hist[ei[e]], 1);
}

__global__ void k_dinv(int n) {
    int i = blockIdx.x * blockDim.x + threadIdx.x;
    if (i < n) g_dinv[i] = rsqrtf((float)g_hist[i] + 1.0f);  // +1 self loop
}

__global__ void k_scan_block(int n) {
    __shared__ int sh[512];
    int gid = blockIdx.x * 512 + threadIdx.x;
    int v = (gid < n) ? g_hist[gid] : 0;
    sh[threadIdx.x] = v;
    __syncthreads();
    #pragma unroll
    for (int off = 1; off < 512; off <<= 1) {
        int t = (threadIdx.x >= off) ? sh[threadIdx.x - off] : 0;
        __syncthreads();
        sh[threadIdx.x] += t;
        __syncthreads();
    }
    if (gid < n) g_rowptr[gid] = sh[threadIdx.x] - v;   // exclusive
    if (threadIdx.x == 511) g_part[blockIdx.x] = sh[511];
}

__global__ void k_scan_part(int nb) {
    if (blockIdx.x == 0 && threadIdx.x == 0) {
        int run = 0;
        for (int b = 0; b < nb; b++) { int t = g_part[b]; g_part[b] = run; run += t; }
    }
}

__global__ void k_scan_add(int n, int Etot) {
    int gid = blockIdx.x * 512 + threadIdx.x;
    if (gid < n) g_rowptr[gid] += g_part[blockIdx.x];
    if (gid == 0) g_rowptr[n] = Etot;
}

__global__ void k_fill(const int* __restrict__ ei, int E) {
    int e = blockIdx.x * blockDim.x + threadIdx.x;
    if (e >= E) return;
    int r = ei[e];
    int c = ei[E + e];
    int pos = g_rowptr[r] + atomicAdd(&g_cnt[r], 1);
    g_col[pos] = c;
    g_w[pos]   = g_dinv[r] * g_dinv[c];
}

// ---------------- SpMM: y_i = dinv_i^2 * x_i + sum_j w_ij x_j ----------------
// one warp per node, 2 features per lane
__global__ void k_spmm(const float* __restrict__ src, float* __restrict__ dst, int n) {
    int warp = (blockIdx.x * blockDim.x + threadIdx.x) >> 5;
    int lane = threadIdx.x & 31;
    if (warp >= n) return;
    int i = warp;
    float d  = g_dinv[i];
    float sw = d * d;
    const float* xr = src + (size_t)i * F;
    float acc0 = sw * xr[lane];
    float acc1 = sw * xr[lane + 32];
    int s = g_rowptr[i], e = g_rowptr[i + 1];
    int p = s;
    // 2-wide to expose some MLP
    for (; p + 2 <= e; p += 2) {
        int   j0 = g_col[p],   j1 = g_col[p + 1];
        float w0 = g_w[p],     w1 = g_w[p + 1];
        const float* x0 = src + (size_t)j0 * F;
        const float* x1 = src + (size_t)j1 * F;
        float a0 = x0[lane], a1 = x0[lane + 32];
        float c0 = x1[lane], c1 = x1[lane + 32];
        acc0 += w0 * a0 + w1 * c0;
        acc1 += w0 * a1 + w1 * c1;
    }
    if (p < e) {
        int j = g_col[p];
        float w = g_w[p];
        acc0 += w * src[(size_t)j * F + lane];
        acc1 += w * src[(size_t)j * F + lane + 32];
    }
    dst[(size_t)i * F + lane]      = acc0;
    dst[(size_t)i * F + lane + 32] = acc1;
}

// ---------------- GEMM1 (64->64) + SELU ----------------
__global__ void k_gemm1(const float* __restrict__ src, float* __restrict__ dst,
                        const float* __restrict__ W1, const float* __restrict__ b1, int n) {
    __shared__ float Ws[F * F];
    for (int t = threadIdx.x; t < F * F; t += blockDim.x) Ws[t] = W1[t];
    __syncthreads();
    int warp = (blockIdx.x * blockDim.x + threadIdx.x) >> 5;
    int lane = threadIdx.x & 31;
    if (warp >= n) return;
    int i = warp;
    float y0 = src[(size_t)i * F + lane];
    float y1 = src[(size_t)i * F + lane + 32];
    float acc0 = b1[lane], acc1 = b1[lane + 32];
    #pragma unroll
    for (int k = 0; k < 32; k++) {
        float yk = __shfl_sync(0xffffffffu, y0, k);
        acc0 += yk * Ws[k * F + lane];
        acc1 += yk * Ws[k * F + lane + 32];
    }
    #pragma unroll
    for (int k = 0; k < 32; k++) {
        float yk = __shfl_sync(0xffffffffu, y1, k);
        acc0 += yk * Ws[(k + 32) * F + lane];
        acc1 += yk * Ws[(k + 32) * F + lane + 32];
    }
    const float al = 1.6732632423543772f, sc = 1.0507009873554805f;
    acc0 = (acc0 > 0.f) ? sc * acc0 : sc * al * expm1f(acc0);
    acc1 = (acc1 > 0.f) ? sc * acc1 : sc * al * expm1f(acc1);
    dst[(size_t)i * F + lane]      = acc0;
    dst[(size_t)i * F + lane + 32] = acc1;
}

// ---------------- GEMM2 (64->16) + log_softmax ----------------
__global__ void k_gemm2(const float* __restrict__ src, float* __restrict__ out,
                        const float* __restrict__ W2, const float* __restrict__ b2, int n) {
    __shared__ float Ws[F * FO];
    __shared__ float bs[FO];
    for (int t = threadIdx.x; t < F * FO; t += blockDim.x) Ws[t] = W2[t];
    if (threadIdx.x < FO) bs[threadIdx.x] = b2[threadIdx.x];
    __syncthreads();
    int warp = (blockIdx.x * blockDim.x + threadIdx.x) >> 5;
    int lane = threadIdx.x & 31;
    if (warp >= n) return;
    int i = warp;
    float h0 = src[(size_t)i * F + lane];
    float h1 = src[(size_t)i * F + lane + 32];
    int f = lane & 15;                 // both 16-lane halves compute identical data
    float acc = bs[f];
    #pragma unroll
    for (int k = 0; k < 32; k++) {
        float hk = __shfl_sync(0xffffffffu, h0, k);
        acc += hk * Ws[k * FO + f];
    }
    #pragma unroll
    for (int k = 0; k < 32; k++) {
        float hk = __shfl_sync(0xffffffffu, h1, k);
        acc += hk * Ws[(k + 32) * FO + f];
    }
    // log_softmax over 16 within each half-warp group
    float m = acc;
    #pragma unroll
    for (int off = 8; off >= 1; off >>= 1)
        m = fmaxf(m, __shfl_xor_sync(0xffffffffu, m, off, 16));
    float ex = expf(acc - m);
    float ssum = ex;
    #pragma unroll
    for (int off = 8; off >= 1; off >>= 1)
        ssum += __shfl_xor_sync(0xffffffffu, ssum, off, 16);
    float res = acc - m - logf(ssum);
    if (lane < 16) out[(size_t)i * FO + lane] = res;
}

// ---------------- launch ----------------
extern "C" void kernel_launch(void* const* d_in, const int* in_sizes, int n_in,
                              void* d_out, int out_size) {
    const float* x  = (const float*)d_in[0];
    const float* W1 = (const float*)d_in[1];
    const float* b1 = (const float*)d_in[2];
    const float* W2 = (const float*)d_in[3];
    const float* b2 = (const float*)d_in[4];
    const int*   ei = (const int*)  d_in[5];
    int N = in_sizes[0] / F;
    int E = in_sizes[5] / 2;
    float* out = (float*)d_out;

    float *bufA, *bufB;
    cudaGetSymbolAddress((void**)&bufA, g_bufA);
    cudaGetSymbolAddress((void**)&bufB, g_bufB);

    int tb = 256;
    int nbN  = (N + tb - 1) / tb;
    int nbE  = (E + tb - 1) / tb;
    int nb512 = (N + 511) / 512;
    int nbW  = (N * 32 + tb - 1) / tb;   // warp-per-node kernels

    // CSR build
    k_init     <<<nbN, tb>>>(N);
    k_hist     <<<nbE, tb>>>(ei, E);
    k_dinv     <<<nbN, tb>>>(N);
    k_scan_block<<<nb512, 512>>>(N);
    k_scan_part<<<1, 32>>>(nb512);
    k_scan_add <<<nb512, 512>>>(N, E);
    k_fill     <<<nbE, tb>>>(ei, E);

    // conv1: 4 hops then linear+selu
    k_spmm<<<nbW, tb>>>(x,    bufA, N);
    k_spmm<<<nbW, tb>>>(bufA, bufB, N);
    k_spmm<<<nbW, tb>>>(bufB, bufA, N);
    k_spmm<<<nbW, tb>>>(bufA, bufB, N);
    k_gemm1<<<nbW, tb>>>(bufB, bufA, W1, b1, N);

    // conv2: 1 hop then linear + log_softmax
    k_spmm<<<nbW, tb>>>(bufA, bufB, N);
    k_gemm2<<<nbW, tb>>>(bufB, out, W2, b2, N);
}

// round 3
// speedup vs baseline: 1.1559x; 1.1559x over previous
#include <cuda_runtime.h>
#include <math.h>

#define NMAX 100000
#define EMAX 1000000
#define F    64
#define FO   16

// ---------------- scratch (no allocations allowed) ----------------
__device__ int   g_hist[NMAX];
__device__ int   g_cnt [NMAX];
__device__ int   g_rowptr[NMAX + 1];
__device__ int   g_col [EMAX];
__device__ float g_w   [EMAX];
__device__ float g_dinv[NMAX];
__device__ float g_bufA[(size_t)NMAX * F];
__device__ float g_bufB[(size_t)NMAX * F];
__device__ int   g_part[1024];

// ---------------- CSR build ----------------
__global__ void k_init(int n) {
    int i = blockIdx.x * blockDim.x + threadIdx.x;
    if (i < n) { g_hist[i] = 0; g_cnt[i] = 0; }
}

__global__ void k_hist(const int* __restrict__ ei, int E) {
    int e = blockIdx.x * blockDim.x + threadIdx.x;
    if (e < E) atomicAdd(&g_hist[ei[e]], 1);
}

__global__ void k_dinv(int n) {
    int i = blockIdx.x * blockDim.x + threadIdx.x;
    if (i < n) g_dinv[i] = rsqrtf((float)g_hist[i] + 1.0f);  // +1 self loop
}

__global__ void k_scan_block(int n) {
    __shared__ int sh[512];
    int gid = blockIdx.x * 512 + threadIdx.x;
    int v = (gid < n) ? g_hist[gid] : 0;
    sh[threadIdx.x] = v;
    __syncthreads();
    #pragma unroll
    for (int off = 1; off < 512; off <<= 1) {
        int t = (threadIdx.x >= off) ? sh[threadIdx.x - off] : 0;
        __syncthreads();
        sh[threadIdx.x] += t;
        __syncthreads();
    }
    if (gid < n) g_rowptr[gid] = sh[threadIdx.x] - v;   // exclusive
    if (threadIdx.x == 511) g_part[blockIdx.x] = sh[511];
}

__global__ void k_scan_part(int nb) {
    if (blockIdx.x == 0 && threadIdx.x == 0) {
        int run = 0;
        for (int b = 0; b < nb; b++) { int t = g_part[b]; g_part[b] = run; run += t; }
    }
}

__global__ void k_scan_add(int n, int Etot) {
    int gid = blockIdx.x * 512 + threadIdx.x;
    if (gid < n) g_rowptr[gid] += g_part[blockIdx.x];
    if (gid == 0) g_rowptr[n] = Etot;
}

__global__ void k_fill(const int* __restrict__ ei, int E) {
    int e = blockIdx.x * blockDim.x + threadIdx.x;
    if (e >= E) return;
    int r = ei[e];
    int c = ei[E + e];
    int pos = g_rowptr[r] + atomicAdd(&g_cnt[r], 1);
    g_col[pos] = c;
    g_w[pos]   = g_dinv[r] * g_dinv[c];
}

// ---------------- SpMM core: one warp per node, float2 per lane ----------------
__device__ __forceinline__ float2 spmm_row(const float* __restrict__ src, int i, int lane) {
    float d  = g_dinv[i];
    float sw = d * d;
    const float2* xs = (const float2*)(src + (size_t)i * F);
    float2 a = xs[lane];
    float accx = sw * a.x, accy = sw * a.y;
    int s = g_rowptr[i], e = g_rowptr[i + 1];
    int p = s;
    for (; p + 4 <= e; p += 4) {
        int   j0 = g_col[p],     j1 = g_col[p + 1], j2 = g_col[p + 2], j3 = g_col[p + 3];
        float w0 = g_w[p],       w1 = g_w[p + 1],   w2 = g_w[p + 2],   w3 = g_w[p + 3];
        float2 v0 = ((const float2*)(src + (size_t)j0 * F))[lane];
        float2 v1 = ((const float2*)(src + (size_t)j1 * F))[lane];
        float2 v2 = ((const float2*)(src + (size_t)j2 * F))[lane];
        float2 v3 = ((const float2*)(src + (size_t)j3 * F))[lane];
        accx += w0 * v0.x + w1 * v1.x + w2 * v2.x + w3 * v3.x;
        accy += w0 * v0.y + w1 * v1.y + w2 * v2.y + w3 * v3.y;
    }
    for (; p < e; p++) {
        int j = g_col[p];
        float w = g_w[p];
        float2 v = ((const float2*)(src + (size_t)j * F))[lane];
        accx += w * v.x;
        accy += w * v.y;
    }
    return make_float2(accx, accy);
}

__global__ void k_spmm(const float* __restrict__ src, float* __restrict__ dst, int n) {
    int warp = (blockIdx.x * blockDim.x + threadIdx.x) >> 5;
    int lane = threadIdx.x & 31;
    if (warp >= n) return;
    float2 acc = spmm_row(src, warp, lane);
    ((float2*)(dst + (size_t)warp * F))[lane] = acc;
}

// ---------------- hop4 fused: SpMM + W1 + SELU + W2 -> N x 16 ----------------
__global__ void k_hop4_fused(const float* __restrict__ src, float* __restrict__ dst16,
                             const float* __restrict__ W1, const float* __restrict__ b1,
                             const float* __restrict__ W2, const float* __restrict__ b2, int n) {
    __shared__ float W1s[F * F];
    __shared__ float W2s[F * FO];
    __shared__ float b2s[FO];
    for (int t = threadIdx.x; t < F * F; t += blockDim.x) W1s[t] = W1[t];
    for (int t = threadIdx.x; t < F * FO; t += blockDim.x) W2s[t] = W2[t];
    if (threadIdx.x < FO) b2s[threadIdx.x] = b2[threadIdx.x];
    __syncthreads();

    int warp = (blockIdx.x * blockDim.x + threadIdx.x) >> 5;
    int lane = threadIdx.x & 31;
    if (warp >= n) return;

    // SpMM: y holds features (2*lane, 2*lane+1)
    float2 y = spmm_row(src, warp, lane);

    // GEMM1: h[f] = b1[f] + sum_k y[k] * W1[k][f], outputs f=lane, f=lane+32
    float h0 = b1[lane], h1 = b1[lane + 32];
    #pragma unroll
    for (int k = 0; k < F; k++) {
        float yk = (k & 1) ? __shfl_sync(0xffffffffu, y.y, k >> 1)
                           : __shfl_sync(0xffffffffu, y.x, k >> 1);
        h0 += yk * W1s[k * F + lane];
        h1 += yk * W1s[k * F + lane + 32];
    }
    const float al = 1.6732632423543772f, sc = 1.0507009873554805f;
    h0 = (h0 > 0.f) ? sc * h0 : sc * al * expm1f(h0);
    h1 = (h1 > 0.f) ? sc * h1 : sc * al * expm1f(h1);

    // GEMM2: z[f2] = b2[f2] + sum_k h[k] * W2[k][f2], f2 = lane & 15
    int f = lane & 15;
    float z = b2s[f];
    #pragma unroll
    for (int k = 0; k < 32; k++) {
        float hk = __shfl_sync(0xffffffffu, h0, k);
        z += hk * W2s[k * FO + f];
    }
    #pragma unroll
    for (int k = 0; k < 32; k++) {
        float hk = __shfl_sync(0xffffffffu, h1, k);
        z += hk * W2s[(k + 32) * FO + f];
    }
    if (lane < 16) dst16[(size_t)warp * FO + lane] = z;
}

// ---------------- final 16-wide hop + log_softmax: half-warp per node ----------------
__global__ void k_hop16(const float* __restrict__ src16, float* __restrict__ out, int n) {
    int tid = blockIdx.x * blockDim.x + threadIdx.x;
    int node = tid >> 4;
    int f = tid & 15;
    if (node >= n) return;
    float d = g_dinv[node];
    float acc = d * d * src16[(size_t)node * FO + f];
    int s = g_rowptr[node], e = g_rowptr[node + 1];
    int p = s;
    for (; p + 4 <= e; p += 4) {
        int   j0 = g_col[p],   j1 = g_col[p + 1], j2 = g_col[p + 2], j3 = g_col[p + 3];
        float w0 = g_w[p],     w1 = g_w[p + 1],   w2 = g_w[p + 2],   w3 = g_w[p + 3];
        float v0 = src16[(size_t)j0 * FO + f];
        float v1 = src16[(size_t)j1 * FO + f];
        float v2 = src16[(size_t)j2 * FO + f];
        float v3 = src16[(size_t)j3 * FO + f];
        acc += w0 * v0 + w1 * v1 + w2 * v2 + w3 * v3;
    }
    for (; p < e; p++)
        acc += g_w[p] * src16[(size_t)g_col[p] * FO + f];

    // log_softmax across the 16 lanes of this half-warp
    float m = acc;
    #pragma unroll
    for (int off = 8; off >= 1; off >>= 1)
        m = fmaxf(m, __shfl_xor_sync(0xffffffffu, m, off, 16));
    float ex = expf(acc - m);
    float ssum = ex;
    #pragma unroll
    for (int off = 8; off >= 1; off >>= 1)
        ssum += __shfl_xor_sync(0xffffffffu, ssum, off, 16);
    out[(size_t)node * FO + f] = acc - m - logf(ssum);
}

// ---------------- launch ----------------
extern "C" void kernel_launch(void* const* d_in, const int* in_sizes, int n_in,
                              void* d_out, int out_size) {
    const float* x  = (const float*)d_in[0];
    const float* W1 = (const float*)d_in[1];
    const float* b1 = (const float*)d_in[2];
    const float* W2 = (const float*)d_in[3];
    const float* b2 = (const float*)d_in[4];
    const int*   ei = (const int*)  d_in[5];
    int N = in_sizes[0] / F;
    int E = in_sizes[5] / 2;
    float* out = (float*)d_out;

    float *bufA, *bufB;
    cudaGetSymbolAddress((void**)&bufA, g_bufA);
    cudaGetSymbolAddress((void**)&bufB, g_bufB);

    int tb = 256;
    int nbN   = (N + tb - 1) / tb;
    int nbE   = (E + tb - 1) / tb;
    int nb512 = (N + 511) / 512;
    int nbW   = (N * 32 + tb - 1) / tb;   // warp-per-node
    int nbH   = (N * 16 + tb - 1) / tb;   // half-warp-per-node

    // CSR build
    k_init      <<<nbN, tb>>>(N);
    k_hist      <<<nbE, tb>>>(ei, E);
    k_dinv      <<<nbN, tb>>>(N);
    k_scan_block<<<nb512, 512>>>(N);
    k_scan_part <<<1, 32>>>(nb512);
    k_scan_add  <<<nb512, 512>>>(N, E);
    k_fill      <<<nbE, tb>>>(ei, E);

    // conv1: hops 1-3, then hop4 fused with GEMM1+SELU+GEMM2 (projection commutes with Â)
    k_spmm<<<nbW, tb>>>(x,    bufA, N);
    k_spmm<<<nbW, tb>>>(bufA, bufB, N);
    k_spmm<<<nbW, tb>>>(bufB, bufA, N);
    k_hop4_fused<<<nbW, tb>>>(bufA, bufB, W1, b1, W2, b2, N);

    // conv2: 16-wide hop + log_softmax
    k_hop16<<<nbH, tb>>>(bufB, out, N);
}

// round 4
// speedup vs baseline: 1.5344x; 1.3274x over previous
#include <cuda_runtime.h>
#include <math.h>

#define NMAX 100000
#define EMAX 1000000
#define F    64
#define FO   16

// ---------------- scratch (no allocations allowed) ----------------
__device__ int   g_hist[NMAX];
__device__ int   g_cnt [NMAX];
__device__ int   g_rowptr[NMAX + 1];
__device__ int   g_col [EMAX];
__device__ float g_w   [EMAX];
__device__ float g_dinv[NMAX];
__device__ float g_bufA[(size_t)NMAX * F];
__device__ float g_bufB[(size_t)NMAX * F];
__device__ int   g_part[1024];

// ---------------- CSR build ----------------
__global__ void k_hist(const int* __restrict__ ei, int E) {
    int e = blockIdx.x * blockDim.x + threadIdx.x;
    if (e < E) atomicAdd(&g_hist[ei[e]], 1);
}

// scan + dinv fused
__global__ void k_scan_block(int n) {
    __shared__ int sh[512];
    int gid = blockIdx.x * 512 + threadIdx.x;
    int v = (gid < n) ? g_hist[gid] : 0;
    if (gid < n) g_dinv[gid] = rsqrtf((float)v + 1.0f);   // +1 self loop
    sh[threadIdx.x] = v;
    __syncthreads();
    #pragma unroll
    for (int off = 1; off < 512; off <<= 1) {
        int t = (threadIdx.x >= off) ? sh[threadIdx.x - off] : 0;
        __syncthreads();
        sh[threadIdx.x] += t;
        __syncthreads();
    }
    if (gid < n) g_rowptr[gid] = sh[threadIdx.x] - v;     // exclusive
    if (threadIdx.x == 511) g_part[blockIdx.x] = sh[511];
}

__global__ void k_scan_part(int nb) {
    if (threadIdx.x == 0) {
        int run = 0;
        for (int b = 0; b < nb; b++) { int t = g_part[b]; g_part[b] = run; run += t; }
    }
}

__global__ void k_scan_add(int n, int Etot) {
    int gid = blockIdx.x * 512 + threadIdx.x;
    if (gid < n) g_rowptr[gid] += g_part[blockIdx.x];
    if (gid == 0) g_rowptr[n] = Etot;
}

__global__ void k_fill(const int* __restrict__ ei, int E) {
    int e = blockIdx.x * blockDim.x + threadIdx.x;
    if (e >= E) return;
    int r = ei[e];
    int c = ei[E + e];
    int pos = g_rowptr[r] + atomicAdd(&g_cnt[r], 1);
    g_col[pos] = c;
    g_w[pos]   = g_dinv[r] * g_dinv[c];
}

// ---------------- SpMM core: half-warp (16 lanes) per node, float4 per lane ----
__device__ __forceinline__ float4 spmm_row4(const float* __restrict__ src, int node, int l16) {
    float d  = g_dinv[node];
    float sw = d * d;
    float4 a = ((const float4*)(src + (size_t)node * F))[l16];
    float4 acc = make_float4(sw * a.x, sw * a.y, sw * a.z, sw * a.w);
    int s = g_rowptr[node], e = g_rowptr[node + 1];
    int p = s;
    for (; p + 4 <= e; p += 4) {
        int   j0 = g_col[p],   j1 = g_col[p + 1], j2 = g_col[p + 2], j3 = g_col[p + 3];
        float w0 = g_w[p],     w1 = g_w[p + 1],   w2 = g_w[p + 2],   w3 = g_w[p + 3];
        float4 v0 = ((const float4*)(src + (size_t)j0 * F))[l16];
        float4 v1 = ((const float4*)(src + (size_t)j1 * F))[l16];
        float4 v2 = ((const float4*)(src + (size_t)j2 * F))[l16];
        float4 v3 = ((const float4*)(src + (size_t)j3 * F))[l16];
        acc.x += w0 * v0.x + w1 * v1.x + w2 * v2.x + w3 * v3.x;
        acc.y += w0 * v0.y + w1 * v1.y + w2 * v2.y + w3 * v3.y;
        acc.z += w0 * v0.z + w1 * v1.z + w2 * v2.z + w3 * v3.z;
        acc.w += w0 * v0.w + w1 * v1.w + w2 * v2.w + w3 * v3.w;
    }
    for (; p < e; p++) {
        int j = g_col[p];
        float w = g_w[p];
        float4 v = ((const float4*)(src + (size_t)j * F))[l16];
        acc.x += w * v.x; acc.y += w * v.y; acc.z += w * v.z; acc.w += w * v.w;
    }
    return acc;
}

__global__ void k_spmm(const float* __restrict__ src, float* __restrict__ dst, int n) {
    int tid  = blockIdx.x * blockDim.x + threadIdx.x;
    int node = tid >> 4;
    int l16  = tid & 15;
    if (node >= n) return;
    float4 acc = spmm_row4(src, node, l16);
    ((float4*)(dst + (size_t)node * F))[l16] = acc;
}

// ---------------- hop4 fused: SpMM + W1 + SELU + W2 -> N x 16 ----------------
// 256 threads = 16 nodes/block, 16 lanes per node; GEMMs staged via smem.
__global__ void k_hop4_fused(const float* __restrict__ src, float* __restrict__ dst16,
                             const float* __restrict__ W1, const float* __restrict__ b1,
                             const float* __restrict__ W2, const float* __restrict__ b2, int n) {
    __shared__ float W1s[F * F];
    __shared__ float W2s[F * FO];
    __shared__ float b2s[FO];
    __shared__ float y_s[16][F];
    __shared__ float h_s[16][F];
    for (int t = threadIdx.x; t < F * F; t += blockDim.x) W1s[t] = W1[t];
    for (int t = threadIdx.x; t < F * FO; t += blockDim.x) W2s[t] = W2[t];
    if (threadIdx.x < FO) b2s[threadIdx.x] = b2[threadIdx.x];
    __syncthreads();

    int nodeL = threadIdx.x >> 4;
    int l16   = threadIdx.x & 15;
    int node  = blockIdx.x * 16 + nodeL;
    if (node >= n) return;

    // SpMM
    float4 y = spmm_row4(src, node, l16);
    ((float4*)y_s[nodeL])[l16] = y;
    __syncwarp();

    // GEMM1: lane l16 computes features l16, l16+16, l16+32, l16+48
    float h0 = b1[l16], h1 = b1[l16 + 16], h2 = b1[l16 + 32], h3 = b1[l16 + 48];
    #pragma unroll 16
    for (int k = 0; k < F; k++) {
        float yk = y_s[nodeL][k];
        h0 += yk * W1s[k * F + l16];
        h1 += yk * W1s[k * F + l16 + 16];
        h2 += yk * W1s[k * F + l16 + 32];
        h3 += yk * W1s[k * F + l16 + 48];
    }
    const float al = 1.6732632423543772f, sc = 1.0507009873554805f;
    h0 = (h0 > 0.f) ? sc * h0 : sc * al * expm1f(h0);
    h1 = (h1 > 0.f) ? sc * h1 : sc * al * expm1f(h1);
    h2 = (h2 > 0.f) ? sc * h2 : sc * al * expm1f(h2);
    h3 = (h3 > 0.f) ? sc * h3 : sc * al * expm1f(h3);
    h_s[nodeL][l16]      = h0;
    h_s[nodeL][l16 + 16] = h1;
    h_s[nodeL][l16 + 32] = h2;
    h_s[nodeL][l16 + 48] = h3;
    __syncwarp();

    // GEMM2: lane l16 computes output feature l16
    float z = b2s[l16];
    #pragma unroll 16
    for (int k = 0; k < F; k++)
        z += h_s[nodeL][k] * W2s[k * FO + l16];
    dst16[(size_t)node * FO + l16] = z;
}

// ---------------- final 16-wide hop + log_softmax: 4 lanes/node, float4 -------
__global__ void k_hop16(const float* __restrict__ src16, float* __restrict__ out, int n) {
    int tid  = blockIdx.x * blockDim.x + threadIdx.x;
    int node = tid >> 2;
    int l4   = tid & 3;
    if (node >= n) return;
    float d = g_dinv[node];
    float sw = d * d;
    float4 a = ((const float4*)(src16 + (size_t)node * FO))[l4];
    float4 acc = make_float4(sw * a.x, sw * a.y, sw * a.z, sw * a.w);
    int s = g_rowptr[node], e = g_rowptr[node + 1];
    int p = s;
    for (; p + 4 <= e; p += 4) {
        int   j0 = g_col[p],   j1 = g_col[p + 1], j2 = g_col[p + 2], j3 = g_col[p + 3];
        float w0 = g_w[p],     w1 = g_w[p + 1],   w2 = g_w[p + 2],   w3 = g_w[p + 3];
        float4 v0 = ((const float4*)(src16 + (size_t)j0 * FO))[l4];
        float4 v1 = ((const float4*)(src16 + (size_t)j1 * FO))[l4];
        float4 v2 = ((const float4*)(src16 + (size_t)j2 * FO))[l4];
        float4 v3 = ((const float4*)(src16 + (size_t)j3 * FO))[l4];
        acc.x += w0 * v0.x + w1 * v1.x + w2 * v2.x + w3 * v3.x;
        acc.y += w0 * v0.y + w1 * v1.y + w2 * v2.y + w3 * v3.y;
        acc.z += w0 * v0.z + w1 * v1.z + w2 * v2.z + w3 * v3.z;
        acc.w += w0 * v0.w + w1 * v1.w + w2 * v2.w + w3 * v3.w;
    }
    for (; p < e; p++) {
        int j = g_col[p];
        float w = g_w[p];
        float4 v = ((const float4*)(src16 + (size_t)j * FO))[l4];
        acc.x += w * v.x; acc.y += w * v.y; acc.z += w * v.z; acc.w += w * v.w;
    }

    // log_softmax over 16 values spread across 4 lanes x 4 components
    float m = fmaxf(fmaxf(acc.x, acc.y), fmaxf(acc.z, acc.w));
    m = fmaxf(m, __shfl_xor_sync(0xffffffffu, m, 1, 4));
    m = fmaxf(m, __shfl_xor_sync(0xffffffffu, m, 2, 4));
    float ssum = expf(acc.x - m) + expf(acc.y - m) + expf(acc.z - m) + expf(acc.w - m);
    ssum += __shfl_xor_sync(0xffffffffu, ssum, 1, 4);
    ssum += __shfl_xor_sync(0xffffffffu, ssum, 2, 4);
    float lse = m + logf(ssum);
    float4 r = make_float4(acc.x - lse, acc.y - lse, acc.z - lse, acc.w - lse);
    ((float4*)(out + (size_t)node * FO))[l4] = r;
}

// ---------------- launch ----------------
extern "C" void kernel_launch(void* const* d_in, const int* in_sizes, int n_in,
                              void* d_out, int out_size) {
    const float* x  = (const float*)d_in[0];
    const float* W1 = (const float*)d_in[1];
    const float* b1 = (const float*)d_in[2];
    const float* W2 = (const float*)d_in[3];
    const float* b2 = (const float*)d_in[4];
    const int*   ei = (const int*)  d_in[5];
    int N = in_sizes[0] / F;
    int E = in_sizes[5] / 2;
    float* out = (float*)d_out;

    float *bufA, *bufB;
    int *histp, *cntp;
    cudaGetSymbolAddress((void**)&bufA, g_bufA);
    cudaGetSymbolAddress((void**)&bufB, g_bufB);
    cudaGetSymbolAddress((void**)&histp, g_hist);
    cudaGetSymbolAddress((void**)&cntp,  g_cnt);

    int tb = 256;
    int nbE   = (E + tb - 1) / tb;
    int nb512 = (N + 511) / 512;
    int nbH   = (N * 16 + tb - 1) / tb;   // half-warp-per-node
    int nbF   = (N + 15) / 16;            // hop4 fused: 16 nodes/block
    int nbQ   = (N * 4 + tb - 1) / tb;    // 4 lanes/node

    // CSR build
    cudaMemsetAsync(histp, 0, (size_t)N * sizeof(int));
    cudaMemsetAsync(cntp,  0, (size_t)N * sizeof(int));
    k_hist      <<<nbE, tb>>>(ei, E);
    k_scan_block<<<nb512, 512>>>(N);
    k_scan_part <<<1, 32>>>(nb512);
    k_scan_add  <<<nb512, 512>>>(N, E);
    k_fill      <<<nbE, tb>>>(ei, E);

    // conv1: hops 1-3, then hop4 fused with GEMM1+SELU+GEMM2 (projection commutes with A_hat)
    k_spmm<<<nbH, tb>>>(x,    bufA, N);
    k_spmm<<<nbH, tb>>>(bufA, bufB, N);
    k_spmm<<<nbH, tb>>>(bufB, bufA, N);
    k_hop4_fused<<<nbF, tb>>>(bufA, bufB, W1, b1, W2, b2, N);

    // conv2: 16-wide hop + log_softmax
    k_hop16<<<nbQ, tb>>>(bufB, out, N);
}

// round 5
// speedup vs baseline: 1.6980x; 1.1066x over previous
#include <cuda_runtime.h>
#include <cuda_fp16.h>
#include <math.h>

#define NMAX 100000
#define EMAX 1000000
#define F    64
#define FO   16

// ---------------- scratch (no allocations allowed) ----------------
__device__ int    g_hist[NMAX];
__device__ int    g_cnt [NMAX];
__device__ int    g_rowptr[NMAX + 1];
__device__ int    g_col [EMAX];
__device__ float  g_w   [EMAX];
__device__ float  g_dinv[NMAX];
__device__ __half g_bufH1[(size_t)NMAX * F];
__device__ __half g_bufH2[(size_t)NMAX * F];
__device__ float  g_buf16[(size_t)NMAX * FO];
__device__ int    g_part[1024];

// ---------------- CSR build ----------------
__global__ void k_hist(const int* __restrict__ ei, int E) {
    int e = blockIdx.x * blockDim.x + threadIdx.x;
    if (e < E) atomicAdd(&g_hist[ei[e]], 1);
}

// scan + dinv fused
__global__ void k_scan_block(int n) {
    __shared__ int sh[512];
    int gid = blockIdx.x * 512 + threadIdx.x;
    int v = (gid < n) ? g_hist[gid] : 0;
    if (gid < n) g_dinv[gid] = rsqrtf((float)v + 1.0f);   // +1 self loop
    sh[threadIdx.x] = v;
    __syncthreads();
    #pragma unroll
    for (int off = 1; off < 512; off <<= 1) {
        int t = (threadIdx.x >= off) ? sh[threadIdx.x - off] : 0;
        __syncthreads();
        sh[threadIdx.x] += t;
        __syncthreads();
    }
    if (gid < n) g_rowptr[gid] = sh[threadIdx.x] - v;     // exclusive
    if (threadIdx.x == 511) g_part[blockIdx.x] = sh[511];
}

__global__ void k_scan_part(int nb) {
    if (threadIdx.x == 0) {
        int run = 0;
        for (int b = 0; b < nb; b++) { int t = g_part[b]; g_part[b] = run; run += t; }
    }
}

__global__ void k_scan_add(int n, int Etot) {
    int gid = blockIdx.x * 512 + threadIdx.x;
    if (gid < n) g_rowptr[gid] += g_part[blockIdx.x];
    if (gid == 0) g_rowptr[n] = Etot;
}

__global__ void k_fill(const int* __restrict__ ei, int E) {
    int e = blockIdx.x * blockDim.x + threadIdx.x;
    if (e >= E) return;
    int r = ei[e];
    int c = ei[E + e];
    int pos = g_rowptr[r] + atomicAdd(&g_cnt[r], 1);
    g_col[pos] = c;
    g_w[pos]   = g_dinv[r] * g_dinv[c];
}

// ---------------- helpers ----------------
__device__ __forceinline__ void h8_acc(uint4 u, float w, float* acc) {
    __half2* h = (__half2*)&u;
    float2 f0 = __half22float2(h[0]);
    float2 f1 = __half22float2(h[1]);
    float2 f2 = __half22float2(h[2]);
    float2 f3 = __half22float2(h[3]);
    acc[0] += w * f0.x; acc[1] += w * f0.y;
    acc[2] += w * f1.x; acc[3] += w * f1.y;
    acc[4] += w * f2.x; acc[5] += w * f2.y;
    acc[6] += w * f3.x; acc[7] += w * f3.y;
}

// fp16 SpMM core: 8 lanes per node, 8 features (one uint4) per lane
__device__ __forceinline__ void spmm_row_h(const __half* __restrict__ src, int node,
                                           int l8, float* acc) {
    float d  = g_dinv[node];
    float sw = d * d;
    const uint4* base = (const uint4*)(src + (size_t)node * F);
    #pragma unroll
    for (int i = 0; i < 8; i++) acc[i] = 0.f;
    h8_acc(base[l8], sw, acc);
    int s = g_rowptr[node], e = g_rowptr[node + 1];
    int p = s;
    for (; p + 4 <= e; p += 4) {
        int   j0 = g_col[p],   j1 = g_col[p + 1], j2 = g_col[p + 2], j3 = g_col[p + 3];
        float w0 = g_w[p],     w1 = g_w[p + 1],   w2 = g_w[p + 2],   w3 = g_w[p + 3];
        uint4 v0 = ((const uint4*)(src + (size_t)j0 * F))[l8];
        uint4 v1 = ((const uint4*)(src + (size_t)j1 * F))[l8];
        uint4 v2 = ((const uint4*)(src + (size_t)j2 * F))[l8];
        uint4 v3 = ((const uint4*)(src + (size_t)j3 * F))[l8];
        h8_acc(v0, w0, acc);
        h8_acc(v1, w1, acc);
        h8_acc(v2, w2, acc);
        h8_acc(v3, w3, acc);
    }
    for (; p < e; p++) {
        uint4 v = ((const uint4*)(src + (size_t)g_col[p] * F))[l8];
        h8_acc(v, g_w[p], acc);
    }
}

__device__ __forceinline__ uint4 f8_to_h8(const float* acc) {
    __half2 h0 = __floats2half2_rn(acc[0], acc[1]);
    __half2 h1 = __floats2half2_rn(acc[2], acc[3]);
    __half2 h2 = __floats2half2_rn(acc[4], acc[5]);
    __half2 h3 = __floats2half2_rn(acc[6], acc[7]);
    uint4 u;
    u.x = *(unsigned*)&h0; u.y = *(unsigned*)&h1;
    u.z = *(unsigned*)&h2; u.w = *(unsigned*)&h3;
    return u;
}

// ---------------- hop1: fp32 gather -> fp16 out (16 lanes/node, float4) -------
__global__ void k_hop1(const float* __restrict__ src, __half* __restrict__ dst, int n) {
    int tid  = blockIdx.x * blockDim.x + threadIdx.x;
    int node = tid >> 4;
    int l16  = tid & 15;
    if (node >= n) return;
    float d  = g_dinv[node];
    float sw = d * d;
    float4 a = ((const float4*)(src + (size_t)node * F))[l16];
    float4 acc = make_float4(sw * a.x, sw * a.y, sw * a.z, sw * a.w);
    int s = g_rowptr[node], e = g_rowptr[node + 1];
    int p = s;
    for (; p + 4 <= e; p += 4) {
        int   j0 = g_col[p],   j1 = g_col[p + 1], j2 = g_col[p + 2], j3 = g_col[p + 3];
        float w0 = g_w[p],     w1 = g_w[p + 1],   w2 = g_w[p + 2],   w3 = g_w[p + 3];
        float4 v0 = ((const float4*)(src + (size_t)j0 * F))[l16];
        float4 v1 = ((const float4*)(src + (size_t)j1 * F))[l16];
        float4 v2 = ((const float4*)(src + (size_t)j2 * F))[l16];
        float4 v3 = ((const float4*)(src + (size_t)j3 * F))[l16];
        acc.x += w0 * v0.x + w1 * v1.x + w2 * v2.x + w3 * v3.x;
        acc.y += w0 * v0.y + w1 * v1.y + w2 * v2.y + w3 * v3.y;
        acc.z += w0 * v0.z + w1 * v1.z + w2 * v2.z + w3 * v3.z;
        acc.w += w0 * v0.w + w1 * v1.w + w2 * v2.w + w3 * v3.w;
    }
    for (; p < e; p++) {
        int j = g_col[p];
        float w = g_w[p];
        float4 v = ((const float4*)(src + (size_t)j * F))[l16];
        acc.x += w * v.x; acc.y += w * v.y; acc.z += w * v.z; acc.w += w * v.w;
    }
    __half2 lo = __floats2half2_rn(acc.x, acc.y);
    __half2 hi = __floats2half2_rn(acc.z, acc.w);
    uint2 u;
    u.x = *(unsigned*)&lo; u.y = *(unsigned*)&hi;
    ((uint2*)(dst + (size_t)node * F))[l16] = u;
}

// ---------------- hops 2,3: fp16 -> fp16 (8 lanes/node) ----------------------
__global__ void k_spmm_h(const __half* __restrict__ src, __half* __restrict__ dst, int n) {
    int tid  = blockIdx.x * blockDim.x + threadIdx.x;
    int node = tid >> 3;
    int l8   = tid & 7;
    if (node >= n) return;
    float acc[8];
    spmm_row_h(src, node, l8, acc);
    ((uint4*)(dst + (size_t)node * F))[l8] = f8_to_h8(acc);
}

// ---------------- hop4 fused: fp16 SpMM + W1 + SELU + W2 -> N x 16 -----------
// 256 threads = 32 nodes/block, 8 lanes per node; GEMMs staged via smem.
#define PAD 4
__global__ void k_hop4_fused(const __half* __restrict__ src, float* __restrict__ dst16,
                             const float* __restrict__ W1, const float* __restrict__ b1,
                             const float* __restrict__ W2, const float* __restrict__ b2, int n) {
    __shared__ float W1s[F * F];
    __shared__ float W2s[F * FO];
    __shared__ float b2s[FO];
    __shared__ float y_s[32][F + PAD];
    __shared__ float h_s[32][F + PAD];
    for (int t = threadIdx.x; t < F * F; t += blockDim.x) W1s[t] = W1[t];
    for (int t = threadIdx.x; t < F * FO; t += blockDim.x) W2s[t] = W2[t];
    if (threadIdx.x < FO) b2s[threadIdx.x] = b2[threadIdx.x];
    __syncthreads();

    int nodeL = threadIdx.x >> 3;
    int l8    = threadIdx.x & 7;
    int node  = blockIdx.x * 32 + nodeL;

    float acc[8];
    #pragma unroll
    for (int i = 0; i < 8; i++) acc[i] = 0.f;
    if (node < n) spmm_row_h(src, node, l8, acc);
    ((float4*)&y_s[nodeL][8 * l8])[0] = make_float4(acc[0], acc[1], acc[2], acc[3]);
    ((float4*)&y_s[nodeL][8 * l8 + 4])[0] = make_float4(acc[4], acc[5], acc[6], acc[7]);
    __syncwarp();

    // GEMM1 + SELU: lane l8 computes features l8 + 8*m, m=0..7
    float h[8];
    #pragma unroll
    for (int m = 0; m < 8; m++) h[m] = b1[l8 + 8 * m];
    #pragma unroll 8
    for (int k = 0; k < F; k++) {
        float yk = y_s[nodeL][k];
        #pragma unroll
        for (int m = 0; m < 8; m++)
            h[m] += yk * W1s[k * F + l8 + 8 * m];
    }
    const float al = 1.6732632423543772f, sc = 1.0507009873554805f;
    #pragma unroll
    for (int m = 0; m < 8; m++) {
        h[m] = (h[m] > 0.f) ? sc * h[m] : sc * al * expm1f(h[m]);
        h_s[nodeL][l8 + 8 * m] = h[m];
    }
    __syncwarp();

    // GEMM2: lane l8 computes output features l8 and l8+8
    float z0 = b2s[l8], z1 = b2s[l8 + 8];
    #pragma unroll 8
    for (int k = 0; k < F; k++) {
        float hk = h_s[nodeL][k];
        z0 += hk * W2s[k * FO + l8];
        z1 += hk * W2s[k * FO + l8 + 8];
    }
    if (node < n) {
        dst16[(size_t)node * FO + l8]     = z0;
        dst16[(size_t)node * FO + l8 + 8] = z1;
    }
}

// ---------------- final 16-wide hop + log_softmax: 4 lanes/node, float4 -------
__global__ void k_hop16(const float* __restrict__ src16, float* __restrict__ out, int n) {
    int tid  = blockIdx.x * blockDim.x + threadIdx.x;
    int node = tid >> 2;
    int l4   = tid & 3;
    if (node >= n) return;
    float d = g_dinv[node];
    float sw = d * d;
    float4 a = ((const float4*)(src16 + (size_t)node * FO))[l4];
    float4 acc = make_float4(sw * a.x, sw * a.y, sw * a.z, sw * a.w);
    int s = g_rowptr[node], e = g_rowptr[node + 1];
    int p = s;
    for (; p + 4 <= e; p += 4) {
        int   j0 = g_col[p],   j1 = g_col[p + 1], j2 = g_col[p + 2], j3 = g_col[p + 3];
        float w0 = g_w[p],     w1 = g_w[p + 1],   w2 = g_w[p + 2],   w3 = g_w[p + 3];
        float4 v0 = ((const float4*)(src16 + (size_t)j0 * FO))[l4];
        float4 v1 = ((const float4*)(src16 + (size_t)j1 * FO))[l4];
        float4 v2 = ((const float4*)(src16 + (size_t)j2 * FO))[l4];
        float4 v3 = ((const float4*)(src16 + (size_t)j3 * FO))[l4];
        acc.x += w0 * v0.x + w1 * v1.x + w2 * v2.x + w3 * v3.x;
        acc.y += w0 * v0.y + w1 * v1.y + w2 * v2.y + w3 * v3.y;
        acc.z += w0 * v0.z + w1 * v1.z + w2 * v2.z + w3 * v3.z;
        acc.w += w0 * v0.w + w1 * v1.w + w2 * v2.w + w3 * v3.w;
    }
    for (; p < e; p++) {
        int j = g_col[p];
        float w = g_w[p];
        float4 v = ((const float4*)(src16 + (size_t)j * FO))[l4];
        acc.x += w * v.x; acc.y += w * v.y; acc.z += w * v.z; acc.w += w * v.w;
    }

    // log_softmax over 16 values spread across 4 lanes x 4 components
    float m = fmaxf(fmaxf(acc.x, acc.y), fmaxf(acc.z, acc.w));
    m = fmaxf(m, __shfl_xor_sync(0xffffffffu, m, 1, 4));
    m = fmaxf(m, __shfl_xor_sync(0xffffffffu, m, 2, 4));
    float ssum = expf(acc.x - m) + expf(acc.y - m) + expf(acc.z - m) + expf(acc.w - m);
    ssum += __shfl_xor_sync(0xffffffffu, ssum, 1, 4);
    ssum += __shfl_xor_sync(0xffffffffu, ssum, 2, 4);
    float lse = m + logf(ssum);
    float4 r = make_float4(acc.x - lse, acc.y - lse, acc.z - lse, acc.w - lse);
    ((float4*)(out + (size_t)node * FO))[l4] = r;
}

// ---------------- launch ----------------
extern "C" void kernel_launch(void* const* d_in, const int* in_sizes, int n_in,
                              void* d_out, int out_size) {
    const float* x  = (const float*)d_in[0];
    const float* W1 = (const float*)d_in[1];
    const float* b1 = (const float*)d_in[2];
    const float* W2 = (const float*)d_in[3];
    const float* b2 = (const float*)d_in[4];
    const int*   ei = (const int*)  d_in[5];
    int N = in_sizes[0] / F;
    int E = in_sizes[5] / 2;
    float* out = (float*)d_out;

    __half *H1, *H2;
    float  *buf16;
    int *histp, *cntp;
    cudaGetSymbolAddress((void**)&H1, g_bufH1);
    cudaGetSymbolAddress((void**)&H2, g_bufH2);
    cudaGetSymbolAddress((void**)&buf16, g_buf16);
    cudaGetSymbolAddress((void**)&histp, g_hist);
    cudaGetSymbolAddress((void**)&cntp,  g_cnt);

    int tb = 256;
    int nbE   = (E + tb - 1) / tb;
    int nb512 = (N + 511) / 512;
    int nbH   = (N * 16 + tb - 1) / tb;   // 16 lanes/node
    int nb8   = (N * 8 + tb - 1) / tb;    // 8 lanes/node
    int nbF   = (N + 31) / 32;            // hop4 fused: 32 nodes/block
    int nbQ   = (N * 4 + tb - 1) / tb;    // 4 lanes/node

    // CSR build
    cudaMemsetAsync(histp, 0, (size_t)N * sizeof(int));
    cudaMemsetAsync(cntp,  0, (size_t)N * sizeof(int));
    k_hist      <<<nbE, tb>>>(ei, E);
    k_scan_block<<<nb512, 512>>>(N);
    k_scan_part <<<1, 32>>>(nb512);
    k_scan_add  <<<nb512, 512>>>(N, E);
    k_fill      <<<nbE, tb>>>(ei, E);

    // conv1: hop1 fp32->fp16, hops 2-3 fp16, hop4 fused with GEMM1+SELU+GEMM2
    k_hop1  <<<nbH, tb>>>(x,  H1, N);
    k_spmm_h<<<nb8, tb>>>(H1, H2, N);
    k_spmm_h<<<nb8, tb>>>(H2, H1, N);
    k_hop4_fused<<<nbF, tb>>>(H1, buf16, W1, b1, W2, b2, N);

    // conv2: 16-wide hop + log_softmax
    k_hop16<<<nbQ, tb>>>(buf16, out, N);
}

// round 7
// speedup vs baseline: 1.7319x; 1.0200x over previous
#include <cuda_runtime.h>
#include <cuda_fp16.h>
#include <math.h>

#define NMAX 100000
#define EMAX 1000000
#define F    64
#define FO   16

// ---------------- scratch (no allocations allowed) ----------------
__device__ int    g_hist[NMAX];
__device__ int    g_cnt [NMAX];
__device__ int    g_rowptr[NMAX + 1];
__device__ int    g_col [EMAX];
__device__ float  g_w   [EMAX];
__device__ float  g_dinv[NMAX];
__device__ __half g_bufH1[(size_t)NMAX * F];
__device__ __half g_bufH2[(size_t)NMAX * F];
__device__ float  g_buf16[(size_t)NMAX * FO];
__device__ int    g_part[1024];

// ---------------- CSR build ----------------
__global__ void k_hist(const int* __restrict__ ei, int E) {
    int e = blockIdx.x * blockDim.x + threadIdx.x;
    if (e < E) atomicAdd(&g_hist[ei[e]], 1);
}

// block-local exclusive scan (1024 threads) + dinv + cnt zeroing
__global__ void k_scan_block(int n) {
    __shared__ int sh[1024];
    int gid = blockIdx.x * 1024 + threadIdx.x;
    int v = (gid < n) ? g_hist[gid] : 0;
    if (gid < n) {
        g_dinv[gid] = rsqrtf((float)v + 1.0f);   // +1 self loop
        g_cnt[gid]  = 0;
    }
    sh[threadIdx.x] = v;
    __syncthreads();
    #pragma unroll
    for (int off = 1; off < 1024; off <<= 1) {
        int t = (threadIdx.x >= off) ? sh[threadIdx.x - off] : 0;
        __syncthreads();
        sh[threadIdx.x] += t;
        __syncthreads();
    }
    if (gid < n) g_rowptr[gid] = sh[threadIdx.x] - v;     // exclusive
    if (threadIdx.x == 1023) g_part[blockIdx.x] = sh[1023];
}

// add sum of partials below this block (fused part-scan), set rowptr[n]
__global__ void k_scan_add(int n, int Etot) {
    __shared__ int sred[1024];
    int v = (threadIdx.x < blockIdx.x) ? g_part[threadIdx.x] : 0;
    sred[threadIdx.x] = v;
    __syncthreads();
    #pragma unroll
    for (int off = 512; off >= 1; off >>= 1) {
        if (threadIdx.x < off) sred[threadIdx.x] += sred[threadIdx.x + off];
        __syncthreads();
    }
    int base = sred[0];
    int gid = blockIdx.x * 1024 + threadIdx.x;
    if (gid < n) g_rowptr[gid] += base;
    if (gid == 0) g_rowptr[n] = Etot;
}

__global__ void k_fill(const int* __restrict__ ei, int E) {
    int e = blockIdx.x * blockDim.x + threadIdx.x;
    if (e >= E) return;
    int r = ei[e];
    int c = ei[E + e];
    int pos = g_rowptr[r] + atomicAdd(&g_cnt[r], 1);
    g_col[pos] = c;
    g_w[pos]   = g_dinv[r] * g_dinv[c];
}

// ---------------- x (fp32) -> fp16 ----------------
__global__ void k_cvt(const float* __restrict__ x, __half* __restrict__ dst, int total4) {
    int i = blockIdx.x * blockDim.x + threadIdx.x;   // one float4 -> half4
    if (i >= total4) return;
    float4 v = ((const float4*)x)[i];
    __half2 lo = __floats2half2_rn(v.x, v.y);
    __half2 hi = __floats2half2_rn(v.z, v.w);
    uint2 u;
    u.x = *(unsigned*)&lo; u.y = *(unsigned*)&hi;
    ((uint2*)dst)[i] = u;
}

// ---------------- fp16 SpMM core: 8 lanes/node, 8 features per lane, unroll 8 --
__device__ __forceinline__ void h8_acc(uint4 u, float w, float* acc) {
    __half2* h = (__half2*)&u;
    float2 f0 = __half22float2(h[0]);
    float2 f1 = __half22float2(h[1]);
    float2 f2 = __half22float2(h[2]);
    float2 f3 = __half22float2(h[3]);
    acc[0] += w * f0.x; acc[1] += w * f0.y;
    acc[2] += w * f1.x; acc[3] += w * f1.y;
    acc[4] += w * f2.x; acc[5] += w * f2.y;
    acc[6] += w * f3.x; acc[7] += w * f3.y;
}

__device__ __forceinline__ void spmm_row_h(const __half* __restrict__ src, int node,
                                           int l8, float* acc) {
    float d  = g_dinv[node];
    float sw = d * d;
    #pragma unroll
    for (int i = 0; i < 8; i++) acc[i] = 0.f;
    h8_acc(((const uint4*)(src + (size_t)node * F))[l8], sw, acc);
    int s = g_rowptr[node], e = g_rowptr[node + 1];
    int p = s;
    for (; p + 8 <= e; p += 8) {
        int jj[8]; float ww[8];
        #pragma unroll
        for (int q = 0; q < 8; q++) { jj[q] = g_col[p + q]; ww[q] = g_w[p + q]; }
        uint4 vv[8];
        #pragma unroll
        for (int q = 0; q < 8; q++)
            vv[q] = ((const uint4*)(src + (size_t)jj[q] * F))[l8];
        #pragma unroll
        for (int q = 0; q < 8; q++)
            h8_acc(vv[q], ww[q], acc);
    }
    if (p + 4 <= e) {
        int jj[4]; float ww[4];
        #pragma unroll
        for (int q = 0; q < 4; q++) { jj[q] = g_col[p + q]; ww[q] = g_w[p + q]; }
        uint4 vv[4];
        #pragma unroll
        for (int q = 0; q < 4; q++)
            vv[q] = ((const uint4*)(src + (size_t)jj[q] * F))[l8];
        #pragma unroll
        for (int q = 0; q < 4; q++)
            h8_acc(vv[q], ww[q], acc);
        p += 4;
    }
    for (; p < e; p++) {
        uint4 v = ((const uint4*)(src + (size_t)g_col[p] * F))[l8];
        h8_acc(v, g_w[p], acc);
    }
}

__device__ __forceinline__ uint4 f8_to_h8(const float* acc) {
    __half2 h0 = __floats2half2_rn(acc[0], acc[1]);
    __half2 h1 = __floats2half2_rn(acc[2], acc[3]);
    __half2 h2 = __floats2half2_rn(acc[4], acc[5]);
    __half2 h3 = __floats2half2_rn(acc[6], acc[7]);
    uint4 u;
    u.x = *(unsigned*)&h0; u.y = *(unsigned*)&h1;
    u.z = *(unsigned*)&h2; u.w = *(unsigned*)&h3;
    return u;
}

__global__ void k_spmm_h(const __half* __restrict__ src, __half* __restrict__ dst, int n) {
    int tid  = blockIdx.x * blockDim.x + threadIdx.x;
    int node = tid >> 3;
    int l8   = tid & 7;
    if (node >= n) return;
    float acc[8];
    spmm_row_h(src, node, l8, acc);
    ((uint4*)(dst + (size_t)node * F))[l8] = f8_to_h8(acc);
}

// ---------------- hop4 fused: fp16 SpMM + W1 + SELU + W2 -> N x 16 -----------
#define PAD 4
__global__ void k_hop4_fused(const __half* __restrict__ src, float* __restrict__ dst16,
                             const float* __restrict__ W1, const float* __restrict__ b1,
                             const float* __restrict__ W2, const float* __restrict__ b2, int n) {
    __shared__ float W1s[F * F];
    __shared__ float W2s[F * FO];
    __shared__ float b2s[FO];
    __shared__ float y_s[32][F + PAD];
    __shared__ float h_s[32][F + PAD];
    for (int t = threadIdx.x; t < F * F; t += blockDim.x) W1s[t] = W1[t];
    for (int t = threadIdx.x; t < F * FO; t += blockDim.x) W2s[t] = W2[t];
    if (threadIdx.x < FO) b2s[threadIdx.x] = b2[threadIdx.x];
    __syncthreads();

    int nodeL = threadIdx.x >> 3;
    int l8    = threadIdx.x & 7;
    int node  = blockIdx.x * 32 + nodeL;

    float acc[8];
    #pragma unroll
    for (int i = 0; i < 8; i++) acc[i] = 0.f;
    if (node < n) spmm_row_h(src, node, l8, acc);
    ((float4*)&y_s[nodeL][8 * l8])[0]     = make_float4(acc[0], acc[1], acc[2], acc[3]);
    ((float4*)&y_s[nodeL][8 * l8 + 4])[0] = make_float4(acc[4], acc[5], acc[6], acc[7]);
    __syncwarp();

    // GEMM1 + SELU: lane l8 computes features l8 + 8*m, m=0..7
    float h[8];
    #pragma unroll
    for (int m = 0; m < 8; m++) h[m] = b1[l8 + 8 * m];
    #pragma unroll 8
    for (int k = 0; k < F; k++) {
        float yk = y_s[nodeL][k];
        #pragma unroll
        for (int m = 0; m < 8; m++)
            h[m] += yk * W1s[k * F + l8 + 8 * m];
    }
    const float al = 1.6732632423543772f, sc = 1.0507009873554805f;
    #pragma unroll
    for (int m = 0; m < 8; m++) {
        h[m] = (h[m] > 0.f) ? sc * h[m] : sc * al * expm1f(h[m]);
        h_s[nodeL][l8 + 8 * m] = h[m];
    }
    __syncwarp();

    // GEMM2: lane l8 computes output features l8 and l8+8
    float z0 = b2s[l8], z1 = b2s[l8 + 8];
    #pragma unroll 8
    for (int k = 0; k < F; k++) {
        float hk = h_s[nodeL][k];
        z0 += hk * W2s[k * FO + l8];
        z1 += hk * W2s[k * FO + l8 + 8];
    }
    if (node < n) {
        dst16[(size_t)node * FO + l8]     = z0;
        dst16[(size_t)node * FO + l8 + 8] = z1;
    }
}

// ---------------- final 16-wide hop + log_softmax: 4 lanes/node, float4 -------
__global__ void k_hop16(const float* __restrict__ src16, float* __restrict__ out, int n) {
    int tid  = blockIdx.x * blockDim.x + threadIdx.x;
    int node = tid >> 2;
    int l4   = tid & 3;
    if (node >= n) return;
    float d = g_dinv[node];
    float sw = d * d;
    float4 a = ((const float4*)(src16 + (size_t)node * FO))[l4];
    float4 acc = make_float4(sw * a.x, sw * a.y, sw * a.z, sw * a.w);
    int s = g_rowptr[node], e = g_rowptr[node + 1];
    int p = s;
    for (; p + 4 <= e; p += 4) {
        int   j0 = g_col[p],   j1 = g_col[p + 1], j2 = g_col[p + 2], j3 = g_col[p + 3];
        float w0 = g_w[p],     w1 = g_w[p + 1],   w2 = g_w[p + 2],   w3 = g_w[p + 3];
        float4 v0 = ((const float4*)(src16 + (size_t)j0 * FO))[l4];
        float4 v1 = ((const float4*)(src16 + (size_t)j1 * FO))[l4];
        float4 v2 = ((const float4*)(src16 + (size_t)j2 * FO))[l4];
        float4 v3 = ((const float4*)(src16 + (size_t)j3 * FO))[l4];
        acc.x += w0 * v0.x + w1 * v1.x + w2 * v2.x + w3 * v3.x;
        acc.y += w0 * v0.y + w1 * v1.y + w2 * v2.y + w3 * v3.y;
        acc.z += w0 * v0.z + w1 * v1.z + w2 * v2.z + w3 * v3.z;
        acc.w += w0 * v0.w + w1 * v1.w + w2 * v2.w + w3 * v3.w;
    }
    for (; p < e; p++) {
        int j = g_col[p];
        float w = g_w[p];
        float4 v = ((const float4*)(src16 + (size_t)j * FO))[l4];
        acc.x += w * v.x; acc.y += w * v.y; acc.z += w * v.z; acc.w += w * v.w;
    }

    float m = fmaxf(fmaxf(acc.x, acc.y), fmaxf(acc.z, acc.w));
    m = fmaxf(m, __shfl_xor_sync(0xffffffffu, m, 1, 4));
    m = fmaxf(m, __shfl_xor_sync(0xffffffffu, m, 2, 4));
    float ssum = expf(acc.x - m) + expf(acc.y - m) + expf(acc.z - m) + expf(acc.w - m);
    ssum += __shfl_xor_sync(0xffffffffu, ssum, 1, 4);
    ssum += __shfl_xor_sync(0xffffffffu, ssum, 2, 4);
    float lse = m + logf(ssum);
    float4 r = make_float4(acc.x - lse, acc.y - lse, acc.z - lse, acc.w - lse);
    ((float4*)(out + (size_t)node * FO))[l4] = r;
}

// ---------------- launch ----------------
extern "C" void kernel_launch(void* const* d_in, const int* in_sizes, int n_in,
                              void* d_out, int out_size) {
    const float* x  = (const float*)d_in[0];
    const float* W1 = (const float*)d_in[1];
    const float* b1 = (const float*)d_in[2];
    const float* W2 = (const float*)d_in[3];
    const float* b2 = (const float*)d_in[4];
    const int*   ei = (const int*)  d_in[5];
    int N = in_sizes[0] / F;
    int E = in_sizes[5] / 2;
    float* out = (float*)d_out;

    __half *H1, *H2;
    float  *buf16;
    int *histp;
    cudaGetSymbolAddress((void**)&H1, g_bufH1);
    cudaGetSymbolAddress((void**)&H2, g_bufH2);
    cudaGetSymbolAddress((void**)&buf16, g_buf16);
    cudaGetSymbolAddress((void**)&histp, g_hist);

    int tb = 256;
    int nbE    = (E + tb - 1) / tb;
    int nb1024 = (N + 1023) / 1024;
    int nbC    = (N * F / 4 + tb - 1) / tb;    // convert: float4 per thread
    int nb8    = (N * 8 + tb - 1) / tb;        // 8 lanes/node
    int nbF    = (N + 31) / 32;                // hop4 fused: 32 nodes/block
    int nbQ    = (N * 4 + tb - 1) / tb;        // 4 lanes/node

    // CSR build
    cudaMemsetAsync(histp, 0, (size_t)N * sizeof(int));
    k_hist      <<<nbE, tb>>>(ei, E);
    k_scan_block<<<nb1024, 1024>>>(N);
    k_scan_add  <<<nb1024, 1024>>>(N, E);
    k_fill      <<<nbE, tb>>>(ei, E);

    // convert x to fp16, then 3 fp16 hops, then hop4 fused with GEMM1+SELU+GEMM2
    k_cvt   <<<nbC, tb>>>(x, H1, N * F / 4);
    k_spmm_h<<<nb8, tb>>>(H1, H2, N);
    k_spmm_h<<<nb8, tb>>>(H2, H1, N);
    k_spmm_h<<<nb8, tb>>>(H1, H2, N);
    k_hop4_fused<<<nbF, tb>>>(H2, buf16, W1, b1, W2, b2, N);

    // conv2: 16-wide hop + log_softmax
    k_hop16<<<nbQ, tb>>>(buf16, out, N);
}